// round 4
// baseline (speedup 1.0000x reference)
#include <cuda_runtime.h>
#include <math.h>

// Problem constants: B=32, H=W=14, C=32, K=64, KS=5, stride=1 -> oh=ow=10, P=100, M=800
#define MU_ELEMS (32*100*64)      // 204800
#define SG_ELEMS (32*100*100*64)  // 20480000

__device__ float g_diag_vals[MU_ELEMS];   // v1 + sp*tr, layout [b][p][k]
__device__ float g_mu_scratch[MU_ELEMS];  // fallback target if harness layout differs

// ---------------------------------------------------------------------------
// Kernel A: mu_out (conv) + diag_vals = dsg @ (w^2 + sp[k])
// grid (oy=10, b=32), 128 threads: tid = k (0..63) + 64*half; half picks ox 0-4 / 5-9
// ---------------------------------------------------------------------------
__global__ __launch_bounds__(128) void kernelA(
    const float* __restrict__ mu_in, const float* __restrict__ Sigma_in,
    const float* __restrict__ w_mu, const float* __restrict__ w_sigma,
    float* __restrict__ mu_out)
{
    __shared__ __align__(16) float smu[2240];  // [ki(5)][x(14)][c(32)] window rows oy..oy+4
    __shared__ __align__(16) float sds[2240];  // same window of diag(Sigma)

    const int b  = blockIdx.y;
    const int oy = blockIdx.x;
    const int tid = threadIdx.x;

    for (int i = tid; i < 2240; i += 128) {
        int ki  = i / 448;          // 14*32
        int rem = i - ki * 448;     // x*32 + c
        int row = oy + ki;
        smu[i] = mu_in[(b * 196 + row * 14) * 32 + rem];
        int x = rem >> 5, c = rem & 31;
        int n = row * 14 + x;
        sds[i] = Sigma_in[(((size_t)b * 196 + n) * 196 + n) * 32 + c];
    }
    __syncthreads();

    const int k   = tid & 63;
    const int oxb = (tid >> 6) * 5;
    const float spk = log1pf(expf(w_sigma[k]));   // softplus

    float accmu[5] = {0.f,0.f,0.f,0.f,0.f};
    float accd [5] = {0.f,0.f,0.f,0.f,0.f};
    const float* wk = w_mu + k;

    #pragma unroll 1
    for (int kk = 0; kk < 25; kk++) {
        const int sb = (kk / 5) * 448 + (kk % 5) * 32;
        const int mb = kk * 32;
        #pragma unroll
        for (int c4 = 0; c4 < 8; c4++) {
            float w0 = wk[(mb + c4*4 + 0) * 64];
            float w1 = wk[(mb + c4*4 + 1) * 64];
            float w2 = wk[(mb + c4*4 + 2) * 64];
            float w3 = wk[(mb + c4*4 + 3) * 64];
            float e0 = fmaf(w0, w0, spk), e1 = fmaf(w1, w1, spk);
            float e2 = fmaf(w2, w2, spk), e3 = fmaf(w3, w3, spk);
            const int s0 = sb + oxb * 32 + c4 * 4;
            #pragma unroll
            for (int j = 0; j < 5; j++) {
                float4 mv = *(const float4*)(smu + s0 + j * 32);
                float4 dv = *(const float4*)(sds + s0 + j * 32);
                accmu[j] = fmaf(mv.x, w0, accmu[j]);
                accmu[j] = fmaf(mv.y, w1, accmu[j]);
                accmu[j] = fmaf(mv.z, w2, accmu[j]);
                accmu[j] = fmaf(mv.w, w3, accmu[j]);
                accd[j]  = fmaf(dv.x, e0, accd[j]);
                accd[j]  = fmaf(dv.y, e1, accd[j]);
                accd[j]  = fmaf(dv.z, e2, accd[j]);
                accd[j]  = fmaf(dv.w, e3, accd[j]);
            }
        }
    }

    float* mo = (mu_out != nullptr) ? mu_out : g_mu_scratch;
    #pragma unroll
    for (int j = 0; j < 5; j++) {
        int p = oy * 10 + oxb + j;
        int o = (b * 100 + p) * 64 + k;
        mo[o]          = accmu[j];
        g_diag_vals[o] = accd[j];
    }
}

// ---------------------------------------------------------------------------
// Kernel B: fused Gram G = mu_p mu_p^T (symmetric tiles) + Sigma_out writer
// grid (pair=15 upper-tri 20x20 tiles, b=32), 128 threads (100 active in GEMM)
// ---------------------------------------------------------------------------
__global__ __launch_bounds__(128) void kernelB(
    const float* __restrict__ mu_in, const float* __restrict__ w_sigma,
    float* __restrict__ sigma_out)
{
    __shared__ __align__(16) float smu[196 * 36];  // mu_in[b] n-major, pad 36 for f4 loads
    __shared__ float sG[400];                      // 20x20 G tile
    __shared__ __align__(16) float ssp[64];        // softplus(w_sigma)

    const int pair = blockIdx.x;
    const int b    = blockIdx.y;
    int pt, qt;
    if      (pair < 5)  { pt = 0; qt = pair;      }
    else if (pair < 9)  { pt = 1; qt = pair - 4;  }
    else if (pair < 12) { pt = 2; qt = pair - 7;  }
    else if (pair < 14) { pt = 3; qt = pair - 9;  }
    else                { pt = 4; qt = 4;         }

    const int tid = threadIdx.x;

    for (int i = tid; i < 6272; i += 128) {
        int n = i >> 5, c = i & 31;
        smu[n * 36 + c] = mu_in[(size_t)(b * 196 + n) * 32 + c];
    }
    if (tid < 64) ssp[tid] = log1pf(expf(w_sigma[tid]));
    __syncthreads();

    if (tid < 100) {
        const int pl = tid % 20, y = tid / 20;   // pl: row in tile; y: q-group of 4
        const int pg = pt * 20 + pl;
        const int np = (pg / 10) * 14 + (pg % 10);
        int nq[4];
        #pragma unroll
        for (int j = 0; j < 4; j++) {
            int qg = qt * 20 + y * 4 + j;
            nq[j] = (qg / 10) * 14 + (qg % 10);
        }
        float acc0 = 0.f, acc1 = 0.f, acc2 = 0.f, acc3 = 0.f;
        #pragma unroll 1
        for (int kk = 0; kk < 25; kk++) {
            const int off = (kk / 5) * 14 + (kk % 5);
            const float* pa  = smu + (np    + off) * 36;
            const float* pb0 = smu + (nq[0] + off) * 36;
            const float* pb1 = smu + (nq[1] + off) * 36;
            const float* pb2 = smu + (nq[2] + off) * 36;
            const float* pb3 = smu + (nq[3] + off) * 36;
            #pragma unroll
            for (int c4 = 0; c4 < 8; c4++) {
                float4 a4 = *(const float4*)(pa  + c4 * 4);
                float4 b0 = *(const float4*)(pb0 + c4 * 4);
                float4 b1 = *(const float4*)(pb1 + c4 * 4);
                float4 b2 = *(const float4*)(pb2 + c4 * 4);
                float4 b3 = *(const float4*)(pb3 + c4 * 4);
                acc0 = fmaf(a4.x, b0.x, acc0); acc0 = fmaf(a4.y, b0.y, acc0);
                acc0 = fmaf(a4.z, b0.z, acc0); acc0 = fmaf(a4.w, b0.w, acc0);
                acc1 = fmaf(a4.x, b1.x, acc1); acc1 = fmaf(a4.y, b1.y, acc1);
                acc1 = fmaf(a4.z, b1.z, acc1); acc1 = fmaf(a4.w, b1.w, acc1);
                acc2 = fmaf(a4.x, b2.x, acc2); acc2 = fmaf(a4.y, b2.y, acc2);
                acc2 = fmaf(a4.z, b2.z, acc2); acc2 = fmaf(a4.w, b2.w, acc2);
                acc3 = fmaf(a4.x, b3.x, acc3); acc3 = fmaf(a4.y, b3.y, acc3);
                acc3 = fmaf(a4.z, b3.z, acc3); acc3 = fmaf(a4.w, b3.w, acc3);
            }
        }
        const int gb = pl * 20 + y * 4;
        sG[gb + 0] = acc0; sG[gb + 1] = acc1; sG[gb + 2] = acc2; sG[gb + 3] = acc3;
    }
    __syncthreads();

    // Write phase: Sigma_out[b,p,q,k] = sp[k]*G[p,q] (+diag_vals on p==q), clean, abs(q==k)
    const float4* sp4 = (const float4*)ssp;
    const float4* dvb = (const float4*)g_diag_vals;
    float4* out4 = (float4*)sigma_out;
    const bool diag = (pt == qt);
    const int P0 = pt * 20, Q0 = qt * 20;

    for (int idx = tid; idx < 6400; idx += 128) {
        const int kq = idx & 15;
        const int t  = idx >> 4;
        const int ql = t % 20, pl = t / 20;
        const int pg = P0 + pl, qg = Q0 + ql;
        const float g = sG[pl * 20 + ql];
        const float4 s4 = sp4[kq];
        float4 v;
        v.x = s4.x * g; v.y = s4.y * g; v.z = s4.z * g; v.w = s4.w * g;
        if (diag && pg == qg) {
            float4 dv = dvb[(b * 100 + pg) * 16 + kq];
            v.x += dv.x; v.y += dv.y; v.z += dv.z; v.w += dv.w;
        }
        v.x = isfinite(v.x) ? v.x : 0.f;
        v.y = isfinite(v.y) ? v.y : 0.f;
        v.z = isfinite(v.z) ? v.z : 0.f;
        v.w = isfinite(v.w) ? v.w : 0.f;
        float4 v2 = v;
        const int k0 = kq * 4;
        if      (qg == k0    ) v.x = fabsf(v.x);
        else if (qg == k0 + 1) v.y = fabsf(v.y);
        else if (qg == k0 + 2) v.z = fabsf(v.z);
        else if (qg == k0 + 3) v.w = fabsf(v.w);
        out4[((size_t)(b * 100 + pg) * 100 + qg) * 16 + kq] = v;
        if (!diag) {
            // transposed tile: G symmetric, pg'!=qg' so no diag add; abs where pg==k
            if      (pg == k0    ) v2.x = fabsf(v2.x);
            else if (pg == k0 + 1) v2.y = fabsf(v2.y);
            else if (pg == k0 + 2) v2.z = fabsf(v2.z);
            else if (pg == k0 + 3) v2.w = fabsf(v2.w);
            out4[((size_t)(b * 100 + qg) * 100 + pg) * 16 + kq] = v2;
        }
    }
}

// ---------------------------------------------------------------------------
extern "C" void kernel_launch(void* const* d_in, const int* in_sizes, int n_in,
                              void* d_out, int out_size)
{
    // Bind inputs by element count (all four are distinct), falling back to
    // positional order if sizes don't match expectations.
    const float* mu_in    = (const float*)d_in[0];
    const float* Sigma_in = (const float*)d_in[1];
    const float* w_mu     = (const float*)d_in[2];
    const float* w_sigma  = (const float*)d_in[3];
    for (int i = 0; i < n_in && i < 8; i++) {
        switch (in_sizes[i]) {
            case 32*14*14*32:        mu_in    = (const float*)d_in[i]; break; // 200704
            case 39337984:           Sigma_in = (const float*)d_in[i]; break; // 32*196*196*32
            case 5*5*32*64:          w_mu     = (const float*)d_in[i]; break; // 51200
            case 64:                 w_sigma  = (const float*)d_in[i]; break;
            default: break;
        }
    }

    float* out = (float*)d_out;
    float* mu_ptr  = nullptr;
    float* sig_ptr = nullptr;
    if (out_size == MU_ELEMS + SG_ELEMS) { mu_ptr = out; sig_ptr = out + MU_ELEMS; }
    else if (out_size == SG_ELEMS)       { sig_ptr = out; }                    // sigma only
    else if (out_size == MU_ELEMS)       { mu_ptr = out; }                     // mu only
    else                                 { mu_ptr = out; sig_ptr = out + MU_ELEMS; }

    dim3 gA(10, 32);
    kernelA<<<gA, 128>>>(mu_in, Sigma_in, w_mu, w_sigma, mu_ptr);
    if (sig_ptr) {
        dim3 gB(15, 32);
        kernelB<<<gB, 128>>>(mu_in, w_sigma, sig_ptr);
    }
}